// round 4
// baseline (speedup 1.0000x reference)
#include <cuda_runtime.h>
#include <math_constants.h>
#include <cstdint>

#define BB 1024
#define LL 256
#define DD 64
#define TDIM 100
#define NTHR 64
#define NINT 65
#define NT 1024          // weight-table intervals (table has NT+1 entries)

// Scratch in __device__ globals (no allocations allowed).
__device__ float  g_T[NTHR];            // sorted relu thresholds (INF padded, all > 0)
__device__ float2 g_UV2[NINT * DD];     // [m][j] : (U, V)
__device__ float  g_W[NT + 1];          // weight(t) lookup table over t in [0,2]

// ---------------------------------------------------------------------------
// Setup kernel (single launch):
//   blocks 0..64 : rank-sort thresholds (block 0 publishes g_T), build UV row
//                  m=blockIdx.x with a 4-way-split 64-term reduction
//   blocks 65..69: tabulate weight(t) = sigmoid(sum_k cos(t*w_k+b_k)*wts_k+bts)
// ---------------------------------------------------------------------------
__global__ void setup_kernel(const float* __restrict__ w1,
                             const float* __restrict__ b1,
                             const float* __restrict__ w2,
                             const float* __restrict__ w_time,
                             const float* __restrict__ b_time,
                             const float* __restrict__ w_ts,
                             const float* __restrict__ b_ts) {
    const int blk = blockIdx.x;
    const int tid = threadIdx.x;
    if (blk < NINT) {
        __shared__ float sw1[NTHR], sb1[NTHR], sTin[NTHR], sTs[NTHR];
        __shared__ float2 spart[4 * DD];

        if (tid < NTHR) {
            float w = w1[tid], b = b1[tid];
            sw1[tid] = w; sb1[tid] = b;
            bool crossing = (w > 0.0f && b < 0.0f) || (w < 0.0f && b > 0.0f);
            sTin[tid] = crossing ? (-b / w) : CUDART_INF_F;
        }
        __syncthreads();
        if (tid < NTHR) {
            float t = sTin[tid];
            int rank = 0;
            #pragma unroll
            for (int j = 0; j < NTHR; ++j) {
                float tj = sTin[j];
                rank += (tj < t) || (tj == t && j < tid);
            }
            sTs[rank] = t;
        }
        __syncthreads();
        if (blk == 0 && tid < NTHR) g_T[tid] = sTs[tid];

        const int m = blk;
        float lo = (m == 0)        ? 0.0f         : sTs[m - 1];
        float hi = (m == NINT - 1) ? CUDART_INF_F : sTs[m];
        float mid;
        if (!isfinite(lo))      mid = 1.0f;              // unreachable row
        else if (!isfinite(hi)) mid = lo * 2.0f + 1.0f;  // last reachable interval
        else                    mid = 0.5f * (lo + hi);

        const int j = tid & 63;
        const int q = tid >> 6;          // 4 slices of the k2 range
        float U = 0.0f, V = 0.0f;
        #pragma unroll 4
        for (int k2 = q * 16; k2 < q * 16 + 16; ++k2) {
            float w = sw1[k2], bb = sb1[k2];
            if (fmaf(mid, w, bb) > 0.0f) {
                float w2v = w2[k2 * DD + j];
                U = fmaf(w, w2v, U);
                V = fmaf(bb, w2v, V);
            }
        }
        spart[q * DD + j] = make_float2(U, V);
        __syncthreads();
        if (tid < DD) {
            float2 a = spart[tid], b_ = spart[DD + tid];
            float2 c = spart[2 * DD + tid], d = spart[3 * DD + tid];
            g_UV2[m * DD + tid] =
                make_float2(a.x + b_.x + c.x + d.x, a.y + b_.y + c.y + d.y);
        }
    } else {
        __shared__ float swt[TDIM], sbt[TDIM], sws[TDIM];
        if (tid < TDIM) {
            swt[tid] = w_time[tid];
            sbt[tid] = b_time[tid];
            sws[tid] = w_ts[tid];
        }
        __syncthreads();
        int g = (blk - NINT) * 256 + tid;
        if (g <= NT) {
            float t = (float)g * (2.0f / (float)NT);
            float acc = b_ts[0];
            #pragma unroll 4
            for (int k = 0; k < TDIM; ++k)
                acc = fmaf(__cosf(fmaf(t, swt[k], sbt[k])), sws[k], acc);
            g_W[g] = 1.0f / (1.0f + __expf(-acc));
        }
    }
}

// ---------------------------------------------------------------------------
// Main kernel helpers
// ---------------------------------------------------------------------------
__device__ __forceinline__ unsigned hash_id(int id) {
    return ((unsigned)id * 2654435761u) >> 23;
}

__device__ __forceinline__ void hash_insert(int* keys, int* cnts, int base, int id) {
    if (id == 0) return;
    unsigned slot = hash_id(id) & 511u;
    while (true) {
        int prev = atomicCAS(&keys[base + slot], 0, id);
        if (prev == 0 || prev == id) { atomicAdd(&cnts[base + slot], 1); break; }
        slot = (slot + 1) & 511u;
    }
}

__device__ __forceinline__ int hash_lookup(const int* keys, const int* cnts,
                                           int base, int id) {
    if (id == 0) return 0;
    unsigned slot = hash_id(id) & 511u;
    while (true) {
        int k = keys[base + slot];
        if (k == id) return cnts[base + slot];
        if (k == 0) return 0;
        slot = (slot + 1) & 511u;
    }
}

__device__ __forceinline__ float weight_lookup(float t) {
    float u = t * ((float)NT * 0.5f);
    u = fminf(fmaxf(u, 0.0f), (float)NT - 0.001f);
    int i0 = (int)u;
    float f = u - (float)i0;
    float a  = __ldg(&g_W[i0]);
    float bb = __ldg(&g_W[i0 + 1]);
    return fmaf(f, bb - a, a);
}

// ---------------------------------------------------------------------------
// Main fused kernel. One block per batch row.
// Phase A (thread-per-position): hash counts, table time-weights, x & interval m.
// Phase B (warp-cooperative): fast path (x_sd==0 && x_ds==0, ~97.5%) loads
//   only 2 UV rows + register-cached row 0; slow path loads 4 rows (x==0
//   gathers hit row 0 and are exact: 0*U0 + V0).
// ---------------------------------------------------------------------------
__global__ __launch_bounds__(LL, 5) void tni_main_kernel(
    const int*   __restrict__ src_ids,
    const int*   __restrict__ dst_ids,
    const float* __restrict__ src_times,
    const float* __restrict__ dst_times,
    const float* __restrict__ node_times,
    const float* __restrict__ b2,
    float*       __restrict__ out)
{
    __shared__ float2 sUV[NINT * DD];          // 33,280 B, layout [m][j]
    __shared__ __align__(16) int sHash[2048];  // keys/counts, reused as sx|smv
    __shared__ float sTm[NTHR];

    const int b = blockIdx.x;
    const int i = threadIdx.x;

    // --- preamble: UV table to shared, hash init, thresholds ---
    {
        const float4* srcv = (const float4*)g_UV2;   // 2080 float4
        float4* dstv = (float4*)sUV;
        #pragma unroll
        for (int t = 0; t < 8; ++t) {
            int idx = i + t * LL;
            if (idx < (NINT * DD) / 2) dstv[idx] = srcv[idx];
        }
    }
    #pragma unroll
    for (int t = 0; t < 8; ++t) sHash[i + t * LL] = 0;
    if (i < NTHR) sTm[i] = g_T[i];

    const int sid = src_ids[b * LL + i];
    const int did = dst_ids[b * LL + i];
    __syncthreads();

    // --- hash histogram inserts ---
    int* keys = sHash;
    int* cnts = sHash + 1024;
    hash_insert(keys, cnts, 0,   sid);
    hash_insert(keys, cnts, 512, did);
    __syncthreads();

    // --- lookups ---
    const int css = hash_lookup(keys, cnts, 0,   sid);
    const int csd = hash_lookup(keys, cnts, 512, sid);
    const int cds = hash_lookup(keys, cnts, 0,   did);
    const int cdd = hash_lookup(keys, cnts, 512, did);

    // --- time weights via 1-D lerp table ---
    const float nt = node_times[b];
    const float ws = weight_lookup(nt - src_times[b * LL + i]);
    const float wd = weight_lookup(nt - dst_times[b * LL + i]);

    const float x_ss = (float)css * ws;
    const float x_sd = (float)csd * ws;
    const float x_ds = (float)cds * wd;
    const float x_dd = (float)cdd * wd;

    // --- interval index via branchless binary search (m = #{T < x}) ---
    // All thresholds > 0, so x==0 naturally lands on m=0.
    int m_ss = 0, m_sd = 0, m_ds = 0, m_dd = 0;
    #pragma unroll
    for (int s = 32; s >= 1; s >>= 1) {
        if (sTm[m_ss + s - 1] < x_ss) m_ss += s;
        if (sTm[m_sd + s - 1] < x_sd) m_sd += s;
        if (sTm[m_ds + s - 1] < x_ds) m_ds += s;
        if (sTm[m_dd + s - 1] < x_dd) m_dd += s;
    }
    if (sTm[m_ss] < x_ss) ++m_ss;
    if (sTm[m_sd] < x_sd) ++m_sd;
    if (sTm[m_ds] < x_ds) ++m_ds;
    if (sTm[m_dd] < x_dd) ++m_dd;

    __syncthreads();  // hash region free for reuse

    float4* sx  = (float4*)sHash;          // 4 KB
    int*    smv = sHash + 1024;            // 1 KB
    sx[i]  = make_float4(x_ss, x_sd, x_ds, x_dd);
    smv[i] = m_ss | (m_sd << 8) | (m_ds << 16) | (m_dd << 24);
    __syncthreads();

    // --- Phase B: warp-cooperative epilogue ---
    const int wid  = i >> 5;
    const int lane = i & 31;

    const float2 b2v = __ldg(&((const float2*)b2)[lane]);  // j = 2*lane, 2*lane+1
    const float tb0 = 2.0f * b2v.x;
    const float tb1 = 2.0f * b2v.y;

    const float4* UV = (const float4*)sUV;  // row m: 32 float4s
    const float4 R0 = UV[lane];             // row 0 cached: V0 = (R0.y, R0.w)
    const size_t dst_off = (size_t)BB * LL * DD;

    for (int p0 = 0; p0 < 32; ++p0) {
        const int p = (wid << 5) | p0;
        const float4 xv = sx[p];      // broadcast LDS
        const int mm = smv[p];        // broadcast LDS
        const int ma = mm & 255;
        const int md = (mm >> 24) & 255;
        const size_t rowbase = (((size_t)b * LL + p) * DD) + 2 * lane;

        float rsx, rsy, rdx, rdy;
        // warp-uniform branch (xv broadcast): common pattern loads 2 rows
        if (xv.y == 0.0f && xv.z == 0.0f && xv.x != 0.0f && xv.w != 0.0f) {
            const float4 A  = UV[ma * 32 + lane];
            const float4 Dv = UV[md * 32 + lane];
            rsx = fmaf(xv.x, A.x,  A.y)  + R0.y + tb0;
            rsy = fmaf(xv.x, A.z,  A.w)  + R0.w + tb1;
            rdx = fmaf(xv.w, Dv.x, Dv.y) + R0.y + tb0;
            rdy = fmaf(xv.w, Dv.z, Dv.w) + R0.w + tb1;
        } else {
            const int mb = (mm >> 8)  & 255;
            const int mc = (mm >> 16) & 255;
            const float4 A  = UV[ma * 32 + lane];
            const float4 Bv = UV[mb * 32 + lane];
            const float4 C  = UV[mc * 32 + lane];
            const float4 Dv = UV[md * 32 + lane];
            rsx = fmaf(xv.x, A.x, A.y) + fmaf(xv.y, Bv.x, Bv.y) + tb0;
            rsy = fmaf(xv.x, A.z, A.w) + fmaf(xv.y, Bv.z, Bv.w) + tb1;
            rdx = fmaf(xv.z, C.x, C.y) + fmaf(xv.w, Dv.x, Dv.y) + tb0;
            rdy = fmaf(xv.z, C.z, C.w) + fmaf(xv.w, Dv.z, Dv.w) + tb1;
        }
        *(float2*)(out + rowbase)           = make_float2(rsx, rsy);
        *(float2*)(out + dst_off + rowbase) = make_float2(rdx, rdy);
    }
}

// ---------------------------------------------------------------------------
// Inputs: 0 src_ids, 1 dst_ids, 2 src_times, 3 dst_times, 4 node_times,
// 5 num_nodes (unused), 6 w_time, 7 b_time, 8 w_ts, 9 b_ts, 10 w1, 11 b1,
// 12 w2, 13 b2.  Output: [src_feats (B,L,D); dst_feats (B,L,D)].
// ---------------------------------------------------------------------------
extern "C" void kernel_launch(void* const* d_in, const int* in_sizes, int n_in,
                              void* d_out, int out_size) {
    const int*   src_ids    = (const int*)  d_in[0];
    const int*   dst_ids    = (const int*)  d_in[1];
    const float* src_times  = (const float*)d_in[2];
    const float* dst_times  = (const float*)d_in[3];
    const float* node_times = (const float*)d_in[4];
    const float* w_time     = (const float*)d_in[6];
    const float* b_time     = (const float*)d_in[7];
    const float* w_ts       = (const float*)d_in[8];
    const float* b_ts       = (const float*)d_in[9];
    const float* w1         = (const float*)d_in[10];
    const float* b1         = (const float*)d_in[11];
    const float* w2         = (const float*)d_in[12];
    const float* b2         = (const float*)d_in[13];
    float*       out        = (float*)d_out;

    const int wt_blocks = (NT + 1 + 255) / 256;   // 5
    setup_kernel<<<NINT + wt_blocks, 256>>>(w1, b1, w2, w_time, b_time, w_ts, b_ts);
    tni_main_kernel<<<BB, LL>>>(src_ids, dst_ids, src_times, dst_times,
                                node_times, b2, out);
}

// round 5
// speedup vs baseline: 1.4870x; 1.4870x over previous
#include <cuda_runtime.h>
#include <math_constants.h>
#include <cstdint>

#define BB 1024
#define LL 256
#define DD 64
#define TDIM 100
#define NTHR 64
#define NINT 65
#define NT 1024          // weight-table intervals (table has NT+1 entries)

// Scratch in __device__ globals (no allocations allowed).
__device__ float  g_T[NTHR];            // sorted relu thresholds (INF padded, all > 0)
__device__ float2 g_UV2[NINT * DD];     // [m][j] : (U, V)
__device__ float  g_W[NT + 1];          // weight(t) lookup table over t in [0,2]

// ---------------------------------------------------------------------------
// Setup kernel (single launch) — R4 version, kept (cut overhead 19.3->7.5us):
//   blocks 0..64 : rank-sort thresholds (block 0 publishes g_T), build UV row
//   blocks 65..69: tabulate weight(t) = sigmoid(sum cos(t*w+b)*wts + bts)
// ---------------------------------------------------------------------------
__global__ void setup_kernel(const float* __restrict__ w1,
                             const float* __restrict__ b1,
                             const float* __restrict__ w2,
                             const float* __restrict__ w_time,
                             const float* __restrict__ b_time,
                             const float* __restrict__ w_ts,
                             const float* __restrict__ b_ts) {
    const int blk = blockIdx.x;
    const int tid = threadIdx.x;
    if (blk < NINT) {
        __shared__ float sw1[NTHR], sb1[NTHR], sTin[NTHR], sTs[NTHR];
        __shared__ float2 spart[4 * DD];

        if (tid < NTHR) {
            float w = w1[tid], b = b1[tid];
            sw1[tid] = w; sb1[tid] = b;
            bool crossing = (w > 0.0f && b < 0.0f) || (w < 0.0f && b > 0.0f);
            sTin[tid] = crossing ? (-b / w) : CUDART_INF_F;
        }
        __syncthreads();
        if (tid < NTHR) {
            float t = sTin[tid];
            int rank = 0;
            #pragma unroll
            for (int j = 0; j < NTHR; ++j) {
                float tj = sTin[j];
                rank += (tj < t) || (tj == t && j < tid);
            }
            sTs[rank] = t;
        }
        __syncthreads();
        if (blk == 0 && tid < NTHR) g_T[tid] = sTs[tid];

        const int m = blk;
        float lo = (m == 0)        ? 0.0f         : sTs[m - 1];
        float hi = (m == NINT - 1) ? CUDART_INF_F : sTs[m];
        float mid;
        if (!isfinite(lo))      mid = 1.0f;
        else if (!isfinite(hi)) mid = lo * 2.0f + 1.0f;
        else                    mid = 0.5f * (lo + hi);

        const int j = tid & 63;
        const int q = tid >> 6;
        float U = 0.0f, V = 0.0f;
        #pragma unroll 4
        for (int k2 = q * 16; k2 < q * 16 + 16; ++k2) {
            float w = sw1[k2], bb = sb1[k2];
            if (fmaf(mid, w, bb) > 0.0f) {
                float w2v = w2[k2 * DD + j];
                U = fmaf(w, w2v, U);
                V = fmaf(bb, w2v, V);
            }
        }
        spart[q * DD + j] = make_float2(U, V);
        __syncthreads();
        if (tid < DD) {
            float2 a = spart[tid], b_ = spart[DD + tid];
            float2 c = spart[2 * DD + tid], d = spart[3 * DD + tid];
            g_UV2[m * DD + tid] =
                make_float2(a.x + b_.x + c.x + d.x, a.y + b_.y + c.y + d.y);
        }
    } else {
        __shared__ float swt[TDIM], sbt[TDIM], sws[TDIM];
        if (tid < TDIM) {
            swt[tid] = w_time[tid];
            sbt[tid] = b_time[tid];
            sws[tid] = w_ts[tid];
        }
        __syncthreads();
        int g = (blk - NINT) * 256 + tid;
        if (g <= NT) {
            float t = (float)g * (2.0f / (float)NT);
            float acc = b_ts[0];
            #pragma unroll 4
            for (int k = 0; k < TDIM; ++k)
                acc = fmaf(__cosf(fmaf(t, swt[k], sbt[k])), sws[k], acc);
            g_W[g] = 1.0f / (1.0f + __expf(-acc));
        }
    }
}

// ---------------------------------------------------------------------------
// Main kernel helpers
// ---------------------------------------------------------------------------
__device__ __forceinline__ unsigned hash_id(int id) {
    return ((unsigned)id * 2654435761u) >> 23;
}

__device__ __forceinline__ void hash_insert(int* keys, int* cnts, int base, int id) {
    if (id == 0) return;
    unsigned slot = hash_id(id) & 511u;
    while (true) {
        int prev = atomicCAS(&keys[base + slot], 0, id);
        if (prev == 0 || prev == id) { atomicAdd(&cnts[base + slot], 1); break; }
        slot = (slot + 1) & 511u;
    }
}

__device__ __forceinline__ int hash_lookup(const int* keys, const int* cnts,
                                           int base, int id) {
    if (id == 0) return 0;
    unsigned slot = hash_id(id) & 511u;
    while (true) {
        int k = keys[base + slot];
        if (k == id) return cnts[base + slot];
        if (k == 0) return 0;
        slot = (slot + 1) & 511u;
    }
}

__device__ __forceinline__ float weight_lookup(float t) {
    float u = t * ((float)NT * 0.5f);
    u = fminf(fmaxf(u, 0.0f), (float)NT - 0.001f);
    int i0 = (int)u;
    float f = u - (float)i0;
    float a  = __ldg(&g_W[i0]);
    float bb = __ldg(&g_W[i0 + 1]);
    return fmaf(f, bb - a, a);
}

// Predicated shared v4 load: if cond != 0 load from shared addr, else keep
// fallback. No BSSY — single @p ld.shared; predicated-off => no wavefronts.
__device__ __forceinline__ float4 lds128_pred(uint32_t saddr, float cond, float4 fb) {
    asm volatile(
        "{\n\t"
        ".reg .pred p;\n\t"
        "setp.ne.f32 p, %4, 0f00000000;\n\t"
        "@p ld.shared.v4.f32 {%0, %1, %2, %3}, [%5];\n\t"
        "}"
        : "+f"(fb.x), "+f"(fb.y), "+f"(fb.z), "+f"(fb.w)
        : "f"(cond), "r"(saddr));
    return fb;
}

// ---------------------------------------------------------------------------
// Main fused kernel. One block per batch row.
// Phase A (thread-per-position): hash counts, table time-weights, x & interval m.
// Phase B (warp-cooperative, straight-line): rows A/D always loaded; rows B/C
//   loaded via predicated LDS with register-cached row 0 fallback (exact:
//   x==0 => m=0 and 0*U0 + V0 = V0).
// ---------------------------------------------------------------------------
__global__ __launch_bounds__(LL, 5) void tni_main_kernel(
    const int*   __restrict__ src_ids,
    const int*   __restrict__ dst_ids,
    const float* __restrict__ src_times,
    const float* __restrict__ dst_times,
    const float* __restrict__ node_times,
    const float* __restrict__ b2,
    float*       __restrict__ out)
{
    __shared__ float2 sUV[NINT * DD];          // 33,280 B, layout [m][j]
    __shared__ __align__(16) int sHash[2048];  // keys/counts, reused as sx|smv
    __shared__ float sTm[NTHR];

    const int b = blockIdx.x;
    const int i = threadIdx.x;

    // --- preamble: UV table to shared, hash init, thresholds ---
    {
        const float4* srcv = (const float4*)g_UV2;   // 2080 float4
        float4* dstv = (float4*)sUV;
        #pragma unroll
        for (int t = 0; t < 8; ++t) {
            int idx = i + t * LL;
            if (idx < (NINT * DD) / 2) dstv[idx] = srcv[idx];
        }
    }
    #pragma unroll
    for (int t = 0; t < 8; ++t) sHash[i + t * LL] = 0;
    if (i < NTHR) sTm[i] = g_T[i];

    const int sid = src_ids[b * LL + i];
    const int did = dst_ids[b * LL + i];
    __syncthreads();

    // --- hash histogram inserts ---
    int* keys = sHash;
    int* cnts = sHash + 1024;
    hash_insert(keys, cnts, 0,   sid);
    hash_insert(keys, cnts, 512, did);
    __syncthreads();

    // --- lookups ---
    const int css = hash_lookup(keys, cnts, 0,   sid);
    const int csd = hash_lookup(keys, cnts, 512, sid);
    const int cds = hash_lookup(keys, cnts, 0,   did);
    const int cdd = hash_lookup(keys, cnts, 512, did);

    // --- time weights via 1-D lerp table ---
    const float nt = node_times[b];
    const float ws = weight_lookup(nt - src_times[b * LL + i]);
    const float wd = weight_lookup(nt - dst_times[b * LL + i]);

    const float x_ss = (float)css * ws;
    const float x_sd = (float)csd * ws;
    const float x_ds = (float)cds * wd;
    const float x_dd = (float)cdd * wd;

    // --- interval index via branchless binary search (m = #{T < x}) ---
    int m_ss = 0, m_sd = 0, m_ds = 0, m_dd = 0;
    #pragma unroll
    for (int s = 32; s >= 1; s >>= 1) {
        if (sTm[m_ss + s - 1] < x_ss) m_ss += s;
        if (sTm[m_sd + s - 1] < x_sd) m_sd += s;
        if (sTm[m_ds + s - 1] < x_ds) m_ds += s;
        if (sTm[m_dd + s - 1] < x_dd) m_dd += s;
    }
    if (sTm[m_ss] < x_ss) ++m_ss;
    if (sTm[m_sd] < x_sd) ++m_sd;
    if (sTm[m_ds] < x_ds) ++m_ds;
    if (sTm[m_dd] < x_dd) ++m_dd;

    __syncthreads();  // hash region free for reuse

    float4* sx  = (float4*)sHash;          // 4 KB
    int*    smv = sHash + 1024;            // 1 KB
    sx[i]  = make_float4(x_ss, x_sd, x_ds, x_dd);
    smv[i] = m_ss | (m_sd << 8) | (m_ds << 16) | (m_dd << 24);
    __syncthreads();

    // --- Phase B: warp-cooperative epilogue ---
    const int wid  = i >> 5;
    const int lane = i & 31;

    const float2 b2v = __ldg(&((const float2*)b2)[lane]);  // j = 2*lane, 2*lane+1
    const float tb0 = 2.0f * b2v.x;
    const float tb1 = 2.0f * b2v.y;

    const float4* UV = (const float4*)sUV;  // row m: 32 float4s
    const uint32_t uv_s = (uint32_t)__cvta_generic_to_shared(sUV);
    const float4 R0 = UV[lane];             // row 0 cached
    const size_t dst_off = (size_t)BB * LL * DD;

    #pragma unroll 2
    for (int p0 = 0; p0 < 32; ++p0) {
        const int p = (wid << 5) | p0;
        const float4 xv = sx[p];      // broadcast LDS
        const int mm = smv[p];        // broadcast LDS
        const int ma = mm & 255;
        const int mb = (mm >> 8)  & 255;
        const int mc = (mm >> 16) & 255;
        const int md = (mm >> 24) & 255;

        const float4 A  = UV[ma * 32 + lane];
        const float4 Dv = UV[md * 32 + lane];
        const float4 Bv = lds128_pred(uv_s + (unsigned)(mb * 32 + lane) * 16u, xv.y, R0);
        const float4 C  = lds128_pred(uv_s + (unsigned)(mc * 32 + lane) * 16u, xv.z, R0);

        float2 rs, rd;
        rs.x = fmaf(xv.x, A.x, A.y) + fmaf(xv.y, Bv.x, Bv.y) + tb0;
        rs.y = fmaf(xv.x, A.z, A.w) + fmaf(xv.y, Bv.z, Bv.w) + tb1;
        rd.x = fmaf(xv.z, C.x, C.y) + fmaf(xv.w, Dv.x, Dv.y) + tb0;
        rd.y = fmaf(xv.z, C.z, C.w) + fmaf(xv.w, Dv.z, Dv.w) + tb1;

        const size_t rowbase = (((size_t)b * LL + p) * DD) + 2 * lane;
        *(float2*)(out + rowbase)           = rs;
        *(float2*)(out + dst_off + rowbase) = rd;
    }
}

// ---------------------------------------------------------------------------
// Inputs: 0 src_ids, 1 dst_ids, 2 src_times, 3 dst_times, 4 node_times,
// 5 num_nodes (unused), 6 w_time, 7 b_time, 8 w_ts, 9 b_ts, 10 w1, 11 b1,
// 12 w2, 13 b2.  Output: [src_feats (B,L,D); dst_feats (B,L,D)].
// ---------------------------------------------------------------------------
extern "C" void kernel_launch(void* const* d_in, const int* in_sizes, int n_in,
                              void* d_out, int out_size) {
    const int*   src_ids    = (const int*)  d_in[0];
    const int*   dst_ids    = (const int*)  d_in[1];
    const float* src_times  = (const float*)d_in[2];
    const float* dst_times  = (const float*)d_in[3];
    const float* node_times = (const float*)d_in[4];
    const float* w_time     = (const float*)d_in[6];
    const float* b_time     = (const float*)d_in[7];
    const float* w_ts       = (const float*)d_in[8];
    const float* b_ts       = (const float*)d_in[9];
    const float* w1         = (const float*)d_in[10];
    const float* b1         = (const float*)d_in[11];
    const float* w2         = (const float*)d_in[12];
    const float* b2         = (const float*)d_in[13];
    float*       out        = (float*)d_out;

    const int wt_blocks = (NT + 1 + 255) / 256;   // 5
    setup_kernel<<<NINT + wt_blocks, 256>>>(w1, b1, w2, w_time, b_time, w_ts, b_ts);
    tni_main_kernel<<<BB, LL>>>(src_ids, dst_ids, src_times, dst_times,
                                node_times, b2, out);
}

// round 6
// speedup vs baseline: 1.5601x; 1.0491x over previous
#include <cuda_runtime.h>
#include <cuda_fp16.h>
#include <math_constants.h>
#include <cstdint>

#define BB 1024
#define LL 256
#define DD 64
#define TDIM 100
#define NTHR 64
#define NINT 65
#define NT 1024          // weight-table intervals (table has NT+1 entries)

// Scratch in __device__ globals (no allocations allowed).
__device__ float  g_T[NTHR];                         // sorted thresholds (INF pad, >0)
__device__ __align__(16) uint32_t g_UVh[NINT * DD];  // half2(U,V) per [m][j]
__device__ float  g_W[NT + 1];                       // weight(t) table, t in [0,2]

// ---------------------------------------------------------------------------
// Setup kernel (single launch):
//   blocks 0..64 : rank-sort thresholds (block 0 publishes g_T), build UV row
//                  m=blockIdx.x (fp32 accumulation, stored as half2(U,V))
//   blocks 65..69: tabulate weight(t) = sigmoid(sum cos(t*w+b)*wts + bts)
// ---------------------------------------------------------------------------
__global__ void setup_kernel(const float* __restrict__ w1,
                             const float* __restrict__ b1,
                             const float* __restrict__ w2,
                             const float* __restrict__ w_time,
                             const float* __restrict__ b_time,
                             const float* __restrict__ w_ts,
                             const float* __restrict__ b_ts) {
    const int blk = blockIdx.x;
    const int tid = threadIdx.x;
    if (blk < NINT) {
        __shared__ float sw1[NTHR], sb1[NTHR], sTin[NTHR], sTs[NTHR];
        __shared__ float2 spart[4 * DD];

        if (tid < NTHR) {
            float w = w1[tid], b = b1[tid];
            sw1[tid] = w; sb1[tid] = b;
            bool crossing = (w > 0.0f && b < 0.0f) || (w < 0.0f && b > 0.0f);
            sTin[tid] = crossing ? (-b / w) : CUDART_INF_F;
        }
        __syncthreads();
        if (tid < NTHR) {
            float t = sTin[tid];
            int rank = 0;
            #pragma unroll
            for (int j = 0; j < NTHR; ++j) {
                float tj = sTin[j];
                rank += (tj < t) || (tj == t && j < tid);
            }
            sTs[rank] = t;
        }
        __syncthreads();
        if (blk == 0 && tid < NTHR) g_T[tid] = sTs[tid];

        const int m = blk;
        float lo = (m == 0)        ? 0.0f         : sTs[m - 1];
        float hi = (m == NINT - 1) ? CUDART_INF_F : sTs[m];
        float mid;
        if (!isfinite(lo))      mid = 1.0f;
        else if (!isfinite(hi)) mid = lo * 2.0f + 1.0f;
        else                    mid = 0.5f * (lo + hi);

        const int j = tid & 63;
        const int q = tid >> 6;
        float U = 0.0f, V = 0.0f;
        #pragma unroll 4
        for (int k2 = q * 16; k2 < q * 16 + 16; ++k2) {
            float w = sw1[k2], bb = sb1[k2];
            if (fmaf(mid, w, bb) > 0.0f) {
                float w2v = w2[k2 * DD + j];
                U = fmaf(w, w2v, U);
                V = fmaf(bb, w2v, V);
            }
        }
        spart[q * DD + j] = make_float2(U, V);
        __syncthreads();
        if (tid < DD) {
            float2 a = spart[tid], b_ = spart[DD + tid];
            float2 c = spart[2 * DD + tid], d = spart[3 * DD + tid];
            float Uf = a.x + b_.x + c.x + d.x;
            float Vf = a.y + b_.y + c.y + d.y;
            __half2 h = __halves2half2(__float2half_rn(Uf), __float2half_rn(Vf));
            g_UVh[m * DD + tid] = *(const uint32_t*)&h;
        }
    } else {
        __shared__ float swt[TDIM], sbt[TDIM], sws[TDIM];
        if (tid < TDIM) {
            swt[tid] = w_time[tid];
            sbt[tid] = b_time[tid];
            sws[tid] = w_ts[tid];
        }
        __syncthreads();
        int g = (blk - NINT) * 256 + tid;
        if (g <= NT) {
            float t = (float)g * (2.0f / (float)NT);
            float acc = b_ts[0];
            #pragma unroll 4
            for (int k = 0; k < TDIM; ++k)
                acc = fmaf(__cosf(fmaf(t, swt[k], sbt[k])), sws[k], acc);
            g_W[g] = 1.0f / (1.0f + __expf(-acc));
        }
    }
}

// ---------------------------------------------------------------------------
// Main kernel helpers
// ---------------------------------------------------------------------------
__device__ __forceinline__ unsigned hash_id(int id) {
    return ((unsigned)id * 2654435761u) >> 23;
}

__device__ __forceinline__ void hash_insert(int* keys, int* cnts, int base, int id) {
    if (id == 0) return;
    unsigned slot = hash_id(id) & 511u;
    while (true) {
        int prev = atomicCAS(&keys[base + slot], 0, id);
        if (prev == 0 || prev == id) { atomicAdd(&cnts[base + slot], 1); break; }
        slot = (slot + 1) & 511u;
    }
}

__device__ __forceinline__ int hash_lookup(const int* keys, const int* cnts,
                                           int base, int id) {
    if (id == 0) return 0;
    unsigned slot = hash_id(id) & 511u;
    while (true) {
        int k = keys[base + slot];
        if (k == id) return cnts[base + slot];
        if (k == 0) return 0;
        slot = (slot + 1) & 511u;
    }
}

__device__ __forceinline__ float weight_lookup(float t) {
    float u = t * ((float)NT * 0.5f);
    u = fminf(fmaxf(u, 0.0f), (float)NT - 0.001f);
    int i0 = (int)u;
    float f = u - (float)i0;
    float a  = __ldg(&g_W[i0]);
    float bb = __ldg(&g_W[i0 + 1]);
    return fmaf(f, bb - a, a);
}

// Predicated shared v2 load: if cond != 0 load from shared addr, else keep
// fallback. No BSSY; predicated-off => no wavefronts.
__device__ __forceinline__ uint2 lds64_pred(uint32_t saddr, float cond, uint2 fb) {
    asm volatile(
        "{\n\t"
        ".reg .pred p;\n\t"
        "setp.ne.f32 p, %2, 0f00000000;\n\t"
        "@p ld.shared.v2.u32 {%0, %1}, [%3];\n\t"
        "}"
        : "+r"(fb.x), "+r"(fb.y)
        : "f"(cond), "r"(saddr));
    return fb;
}

__device__ __forceinline__ float2 h2f(uint32_t h) {
    return __half22float2(*(const __half2*)&h);
}

// ---------------------------------------------------------------------------
// Main fused kernel. One block per batch row.
// Phase A (thread-per-position): hash counts, table time-weights, x & interval m.
// Phase B (warp-cooperative, straight-line): rows A/D always loaded (LDS.64
//   per lane, half2(U,V) x2); rows B/C predicated with row-0 fallback
//   (exact: x==0 => m=0 and 0*U0 + V0 = V0). All accumulation fp32.
// ---------------------------------------------------------------------------
__global__ __launch_bounds__(LL, 6) void tni_main_kernel(
    const int*   __restrict__ src_ids,
    const int*   __restrict__ dst_ids,
    const float* __restrict__ src_times,
    const float* __restrict__ dst_times,
    const float* __restrict__ node_times,
    const float* __restrict__ b2,
    float*       __restrict__ out)
{
    __shared__ __align__(16) uint32_t sUVh[NINT * DD];  // 16,640 B
    __shared__ __align__(16) int sHash[2048];           // keys/counts -> sx|smv
    __shared__ float sTm[NTHR];

    const int b = blockIdx.x;
    const int i = threadIdx.x;

    // --- preamble: UV table to shared (1040 uint4), hash init, thresholds ---
    {
        const uint4* srcv = (const uint4*)g_UVh;
        uint4* dstv = (uint4*)sUVh;
        #pragma unroll
        for (int t = 0; t < 5; ++t) {
            int idx = i + t * LL;
            if (idx < (NINT * DD) / 4) dstv[idx] = srcv[idx];
        }
    }
    #pragma unroll
    for (int t = 0; t < 8; ++t) sHash[i + t * LL] = 0;
    if (i < NTHR) sTm[i] = g_T[i];

    const int sid = src_ids[b * LL + i];
    const int did = dst_ids[b * LL + i];
    __syncthreads();

    // --- hash histogram inserts ---
    int* keys = sHash;
    int* cnts = sHash + 1024;
    hash_insert(keys, cnts, 0,   sid);
    hash_insert(keys, cnts, 512, did);
    __syncthreads();

    // --- lookups ---
    const int css = hash_lookup(keys, cnts, 0,   sid);
    const int csd = hash_lookup(keys, cnts, 512, sid);
    const int cds = hash_lookup(keys, cnts, 0,   did);
    const int cdd = hash_lookup(keys, cnts, 512, did);

    // --- time weights via 1-D lerp table ---
    const float nt = node_times[b];
    const float ws = weight_lookup(nt - src_times[b * LL + i]);
    const float wd = weight_lookup(nt - dst_times[b * LL + i]);

    const float x_ss = (float)css * ws;
    const float x_sd = (float)csd * ws;
    const float x_ds = (float)cds * wd;
    const float x_dd = (float)cdd * wd;

    // --- interval index via branchless binary search (m = #{T < x}) ---
    int m_ss = 0, m_sd = 0, m_ds = 0, m_dd = 0;
    #pragma unroll
    for (int s = 32; s >= 1; s >>= 1) {
        if (sTm[m_ss + s - 1] < x_ss) m_ss += s;
        if (sTm[m_sd + s - 1] < x_sd) m_sd += s;
        if (sTm[m_ds + s - 1] < x_ds) m_ds += s;
        if (sTm[m_dd + s - 1] < x_dd) m_dd += s;
    }
    if (sTm[m_ss] < x_ss) ++m_ss;
    if (sTm[m_sd] < x_sd) ++m_sd;
    if (sTm[m_ds] < x_ds) ++m_ds;
    if (sTm[m_dd] < x_dd) ++m_dd;

    __syncthreads();  // hash region free for reuse

    float4* sx  = (float4*)sHash;          // 4 KB
    int*    smv = sHash + 1024;            // 1 KB
    sx[i]  = make_float4(x_ss, x_sd, x_ds, x_dd);
    smv[i] = m_ss | (m_sd << 8) | (m_ds << 16) | (m_dd << 24);
    __syncthreads();

    // --- Phase B: warp-cooperative epilogue ---
    const int wid  = i >> 5;
    const int lane = i & 31;

    const float2 b2v = __ldg(&((const float2*)b2)[lane]);  // j = 2*lane, 2*lane+1
    const float tb0 = 2.0f * b2v.x;
    const float tb1 = 2.0f * b2v.y;

    const uint32_t uv_s = (uint32_t)__cvta_generic_to_shared(sUVh);
    const uint32_t lane_off = (uint32_t)lane * 8u;           // byte offset within row
    const uint2 R0 = *(const uint2*)&sUVh[2 * lane];         // row 0 fallback
    const size_t dst_off = (size_t)BB * LL * DD;

    #pragma unroll 2
    for (int p0 = 0; p0 < 32; ++p0) {
        const int p = (wid << 5) | p0;
        const float4 xv = sx[p];      // broadcast LDS
        const int mm = smv[p];        // broadcast LDS
        const int ma = mm & 255;
        const int mb = (mm >> 8)  & 255;
        const int mc = (mm >> 16) & 255;
        const int md = (mm >> 24) & 255;

        const uint2 Au = *(const uint2*)&sUVh[ma * DD + 2 * lane];
        const uint2 Du = *(const uint2*)&sUVh[md * DD + 2 * lane];
        const uint2 Bu = lds64_pred(uv_s + (unsigned)mb * (DD * 4) + lane_off, xv.y, R0);
        const uint2 Cu = lds64_pred(uv_s + (unsigned)mc * (DD * 4) + lane_off, xv.z, R0);

        const float2 a0 = h2f(Au.x), a1 = h2f(Au.y);
        const float2 d0 = h2f(Du.x), d1 = h2f(Du.y);
        const float2 b0 = h2f(Bu.x), b1_ = h2f(Bu.y);
        const float2 c0 = h2f(Cu.x), c1 = h2f(Cu.y);

        float2 rs, rd;
        rs.x = fmaf(xv.x, a0.x, a0.y) + fmaf(xv.y, b0.x,  b0.y)  + tb0;
        rs.y = fmaf(xv.x, a1.x, a1.y) + fmaf(xv.y, b1_.x, b1_.y) + tb1;
        rd.x = fmaf(xv.z, c0.x, c0.y) + fmaf(xv.w, d0.x,  d0.y)  + tb0;
        rd.y = fmaf(xv.z, c1.x, c1.y) + fmaf(xv.w, d1.x,  d1.y)  + tb1;

        const size_t rowbase = (((size_t)b * LL + p) * DD) + 2 * lane;
        *(float2*)(out + rowbase)           = rs;
        *(float2*)(out + dst_off + rowbase) = rd;
    }
}

// ---------------------------------------------------------------------------
// Inputs: 0 src_ids, 1 dst_ids, 2 src_times, 3 dst_times, 4 node_times,
// 5 num_nodes (unused), 6 w_time, 7 b_time, 8 w_ts, 9 b_ts, 10 w1, 11 b1,
// 12 w2, 13 b2.  Output: [src_feats (B,L,D); dst_feats (B,L,D)].
// ---------------------------------------------------------------------------
extern "C" void kernel_launch(void* const* d_in, const int* in_sizes, int n_in,
                              void* d_out, int out_size) {
    const int*   src_ids    = (const int*)  d_in[0];
    const int*   dst_ids    = (const int*)  d_in[1];
    const float* src_times  = (const float*)d_in[2];
    const float* dst_times  = (const float*)d_in[3];
    const float* node_times = (const float*)d_in[4];
    const float* w_time     = (const float*)d_in[6];
    const float* b_time     = (const float*)d_in[7];
    const float* w_ts       = (const float*)d_in[8];
    const float* b_ts       = (const float*)d_in[9];
    const float* w1         = (const float*)d_in[10];
    const float* b1         = (const float*)d_in[11];
    const float* w2         = (const float*)d_in[12];
    const float* b2         = (const float*)d_in[13];
    float*       out        = (float*)d_out;

    const int wt_blocks = (NT + 1 + 255) / 256;   // 5
    setup_kernel<<<NINT + wt_blocks, 256>>>(w1, b1, w2, w_time, b_time, w_ts, b_ts);
    tni_main_kernel<<<BB, LL>>>(src_ids, dst_ids, src_times, dst_times,
                                node_times, b2, out);
}